// round 2
// baseline (speedup 1.0000x reference)
#include <cuda_runtime.h>
#include <math.h>

#define TT   256
#define BB   128
#define DD   1024
#define HH   1024
#define DH   2048
#define N4H  4096
#define BH   (BB*HH)

typedef unsigned long long ull;

// Scratch (device globals — no allocation allowed)
__device__ float g_pre[(size_t)TT * BB * N4H];  // x-projection + bias, [T*B, 4H] (gate-major: f,i,g,o)
__device__ float g_c[BH];                        // cell state [b, j]
__device__ float g_hT[HH * BB];                  // transposed hidden state [j, b]

// ---- packed fp32x2 helpers (sm_103a dual fp32 pipe; ptxas never auto-fuses) ----
__device__ __forceinline__ ull pack2(float lo, float hi) {
    ull r; asm("mov.b64 %0, {%1, %2};" : "=l"(r) : "f"(lo), "f"(hi)); return r;
}
__device__ __forceinline__ void unpack2(ull v, float& lo, float& hi) {
    asm("mov.b64 {%0, %1}, %2;" : "=f"(lo), "=f"(hi) : "l"(v));
}
__device__ __forceinline__ ull fma2(ull a, ull b, ull c) {
    ull d; asm("fma.rn.f32x2 %0, %1, %2, %3;" : "=l"(d) : "l"(a), "l"(b), "l"(c)); return d;
}
__device__ __forceinline__ float sigmoidf_(float x) { return 1.0f / (1.0f + expf(-x)); }

// ============================================================================
// Pre-GEMM: g_pre[T*B, 4H] = X[T*B, D] @ Wx^T + bias
// 128x128 tile, BK=8, 256 threads, 8x8 per thread (f32x2-packed).
// Each 128-col tile lies entirely inside one gate (128 | 1024).
// ============================================================================
__global__ __launch_bounds__(256, 2) void pre_gemm_kernel(
    const float* __restrict__ X,
    const float* __restrict__ Wf, const float* __restrict__ Wi,
    const float* __restrict__ Wg, const float* __restrict__ Wo,
    const float* __restrict__ bf, const float* __restrict__ bi,
    const float* __restrict__ bg, const float* __restrict__ bo)
{
    __shared__ float As[8][128];
    __shared__ float Bs[8][128];

    const int tid = threadIdx.x;
    const int bm  = blockIdx.y * 128;
    const int bn  = blockIdx.x * 128;
    const int gate = bn >> 10;

    const float* Wt = (gate == 0) ? Wf : (gate == 1) ? Wi : (gate == 2) ? Wg : Wo;
    const float* bt = (gate == 0) ? bf : (gate == 1) ? bi : (gate == 2) ? bg : bo;

    const int arow = tid >> 1;
    const int ka   = (tid & 1) * 4;
    const int ncol = tid >> 1;
    const int kb   = (tid & 1) * 4;
    const float* wrow = Wt + (size_t)((bn & 1023) + ncol) * DH;   // x-part: cols [0,D)
    const float* xrow = X  + (size_t)(bm + arow) * DD;

    const int tx = tid & 15, ty = tid >> 4;

    ull accp[8][4];
#pragma unroll
    for (int i = 0; i < 8; i++)
#pragma unroll
        for (int jp = 0; jp < 4; jp++) accp[i][jp] = 0ULL;

    // software-pipelined tile loads
    float4 va = *(const float4*)(xrow + ka);
    float4 vb = *(const float4*)(wrow + kb);

    for (int k0 = 0; k0 < DD; k0 += 8) {
        As[ka+0][arow] = va.x; As[ka+1][arow] = va.y; As[ka+2][arow] = va.z; As[ka+3][arow] = va.w;
        Bs[kb+0][ncol] = vb.x; Bs[kb+1][ncol] = vb.y; Bs[kb+2][ncol] = vb.z; Bs[kb+3][ncol] = vb.w;
        __syncthreads();
        if (k0 + 8 < DD) {
            va = *(const float4*)(xrow + k0 + 8 + ka);
            vb = *(const float4*)(wrow + k0 + 8 + kb);
        }
#pragma unroll
        for (int kk = 0; kk < 8; kk++) {
            float4 a0 = *(const float4*)&As[kk][ty*8];
            float4 a1 = *(const float4*)&As[kk][ty*8 + 4];
            ull b[4];
#pragma unroll
            for (int jp = 0; jp < 4; jp++)
                b[jp] = *(const ull*)&Bs[kk][tx*8 + jp*2];
            float as[8] = {a0.x, a0.y, a0.z, a0.w, a1.x, a1.y, a1.z, a1.w};
#pragma unroll
            for (int i = 0; i < 8; i++) {
                ull a2 = pack2(as[i], as[i]);
#pragma unroll
                for (int jp = 0; jp < 4; jp++)
                    accp[i][jp] = fma2(a2, b[jp], accp[i][jp]);
            }
        }
        __syncthreads();
    }

    float biasv[8];
#pragma unroll
    for (int j = 0; j < 8; j++)
        biasv[j] = bt[(bn & 1023) + tx*8 + j];

#pragma unroll
    for (int i = 0; i < 8; i++) {
        size_t r = (size_t)(bm + ty*8 + i);
        float o[8];
#pragma unroll
        for (int jp = 0; jp < 4; jp++) unpack2(accp[i][jp], o[jp*2], o[jp*2+1]);
#pragma unroll
        for (int j = 0; j < 8; j++) o[j] += biasv[j];
        float4* dst = (float4*)&g_pre[r * N4H + bn + tx*8];
        dst[0] = make_float4(o[0], o[1], o[2], o[3]);
        dst[1] = make_float4(o[4], o[5], o[6], o[7]);
    }
}

// ============================================================================
// Per-step kernel. Block = all 128 b-rows x (4 gates x 8 j-cols).
// GEMM gates += h_{t-1} @ Wh^T, then fused cell update.
// h read from g_hT (pre-transposed by step t-1) -> conflict-free vector STS.
// ============================================================================
__global__ __launch_bounds__(256) void lstm_step_kernel(
    const float* __restrict__ Wf, const float* __restrict__ Wi,
    const float* __restrict__ Wg, const float* __restrict__ Wo,
    int t, float* __restrict__ out)
{
    __shared__ float Hs[16][128];
    __shared__ float Ws[16][34];    // pitch 34: conflict-free stores, 8B-aligned pair reads
    __shared__ float Gs[128][33];   // padded gates buffer for epilogue

    const int tid = threadIdx.x;
    const int j0  = blockIdx.x * 8;
    const int rg  = tid >> 3;   // 0..31, 4 rows each
    const int cg  = tid & 7;    // 0..7,  4 cols each

    // Prefetch the pre-activation tile for this thread (hides DRAM latency under GEMM)
    const float* preb = g_pre + (size_t)t * BB * N4H;
    float pre_r[4][4];
#pragma unroll
    for (int i = 0; i < 4; i++) {
        int row = rg*4 + i;
#pragma unroll
        for (int j = 0; j < 4; j++) {
            int col = cg*4 + j;
            int gate = col >> 3, jl = col & 7;
            pre_r[i][j] = preb[(size_t)row * N4H + gate*1024 + j0 + jl];
        }
    }

    ull accp[4][2] = {{0ULL,0ULL},{0ULL,0ULL},{0ULL,0ULL},{0ULL,0ULL}};

    if (t > 0) {
        const int hk   = tid >> 4;          // 0..15 (k within tile)
        const int hseg = (tid & 15) * 8;    // 0..120 (b segment)
        const int wn   = tid >> 2;          // 0..31 column (threads <128)
        const int wkk  = (tid & 3) * 4;
        const float* wrow = Wf;             // init to something valid
        if (tid < 128) {
            int gate = wn >> 3, jl = wn & 7;
            const float* Wt = (gate == 0) ? Wf : (gate == 1) ? Wi : (gate == 2) ? Wg : Wo;
            wrow = Wt + (size_t)(j0 + jl) * DH + DD;   // recurrent part: cols [D, D+H)
        }

        float4 h0 = *(const float4*)&g_hT[(size_t)hk * BB + hseg];
        float4 h1 = *(const float4*)&g_hT[(size_t)hk * BB + hseg + 4];
        float4 wv = make_float4(0.f, 0.f, 0.f, 0.f);
        if (tid < 128) wv = *(const float4*)(wrow + wkk);

        for (int k0 = 0; k0 < HH; k0 += 16) {
            *(float4*)&Hs[hk][hseg]     = h0;
            *(float4*)&Hs[hk][hseg + 4] = h1;
            if (tid < 128) {
                Ws[wkk+0][wn] = wv.x; Ws[wkk+1][wn] = wv.y;
                Ws[wkk+2][wn] = wv.z; Ws[wkk+3][wn] = wv.w;
            }
            __syncthreads();
            if (k0 + 16 < HH) {
                h0 = *(const float4*)&g_hT[(size_t)(k0 + 16 + hk) * BB + hseg];
                h1 = *(const float4*)&g_hT[(size_t)(k0 + 16 + hk) * BB + hseg + 4];
                if (tid < 128) wv = *(const float4*)(wrow + k0 + 16 + wkk);
            }
#pragma unroll
            for (int kk = 0; kk < 16; kk++) {
                float4 av = *(const float4*)&Hs[kk][rg*4];
                ull b0 = *(const ull*)&Ws[kk][cg*4];
                ull b1 = *(const ull*)&Ws[kk][cg*4 + 2];
                float as[4] = {av.x, av.y, av.z, av.w};
#pragma unroll
                for (int i = 0; i < 4; i++) {
                    ull a2 = pack2(as[i], as[i]);
                    accp[i][0] = fma2(a2, b0, accp[i][0]);
                    accp[i][1] = fma2(a2, b1, accp[i][1]);
                }
            }
            __syncthreads();
        }
    }

    // stash gates (recurrent + pre) into smem so each (b,j) sees all 4 gates
#pragma unroll
    for (int i = 0; i < 4; i++) {
        int row = rg*4 + i;
        float o[4];
        unpack2(accp[i][0], o[0], o[1]);
        unpack2(accp[i][1], o[2], o[3]);
#pragma unroll
        for (int j = 0; j < 4; j++)
            Gs[row][cg*4 + j] = o[j] + pre_r[i][j];
    }
    __syncthreads();

    // fused cell update: 1024 (b,j) pairs, 4 per thread
#pragma unroll
    for (int pp = 0; pp < 4; pp++) {
        int p  = tid + pp * 256;
        int b  = p >> 3;
        int jl = p & 7;
        float fg = sigmoidf_(Gs[b][jl]);
        float ig = sigmoidf_(Gs[b][8  + jl]);
        float gg = tanhf   (Gs[b][16 + jl]);
        float og = sigmoidf_(Gs[b][24 + jl]);
        int cidx = b * HH + j0 + jl;
        float cold = (t > 0) ? g_c[cidx] : 0.0f;
        float cnew = fg * cold + ig * gg;
        float h    = og * tanhf(cnew);
        g_c[cidx] = cnew;
        g_hT[(size_t)(j0 + jl) * BB + b] = h;          // transposed for next step
        out[(size_t)t * BH + cidx]       = h;          // outputs[t]
    }
}

__global__ void finalize_kernel(float* __restrict__ out, int write_state) {
    int i = blockIdx.x * blockDim.x + threadIdx.x;
    if (i < BH && write_state) {
        out[(size_t)TT * BH + i]       = out[(size_t)(TT - 1) * BH + i];  // hx = outputs[T-1]
        out[(size_t)TT * BH + BH + i]  = g_c[i];                           // cx
    }
}

extern "C" void kernel_launch(void* const* d_in, const int* in_sizes, int n_in,
                              void* d_out, int out_size) {
    const float* X  = (const float*)d_in[0];
    const float* Wf = (const float*)d_in[1];
    const float* bf = (const float*)d_in[2];
    const float* Wi = (const float*)d_in[3];
    const float* bi = (const float*)d_in[4];
    const float* Wg = (const float*)d_in[5];
    const float* bg = (const float*)d_in[6];
    const float* Wo = (const float*)d_in[7];
    const float* bo = (const float*)d_in[8];
    float* out = (float*)d_out;

    // 1) time-parallel input projection (+bias) for all gates
    dim3 pgrid(N4H / 128, (TT * BB) / 128);   // 32 x 256 blocks
    pre_gemm_kernel<<<pgrid, 256>>>(X, Wf, Wi, Wg, Wo, bf, bi, bg, bo);

    // 2) sequential recurrence, one fused kernel per step
    for (int t = 0; t < TT; t++)
        lstm_step_kernel<<<HH / 8, 256>>>(Wf, Wi, Wg, Wo, t, out);

    // 3) final hx / cx
    int ws = (out_size >= TT * BH + 2 * BH) ? 1 : 0;
    finalize_kernel<<<(BH + 255) / 256, 256>>>(out, ws);
}